// round 7
// baseline (speedup 1.0000x reference)
#include <cuda_runtime.h>
#include <cuda_bf16.h>
#include <cstdint>

#define Nn 3072
#define FIN 512
#define NH 8
#define CC 512
#define NC 16
#define LRA 0.2f
#define JSPLIT 3
#define JCHUNK 1024
#define TI 64
#define TJ 32
#define NT3 32
#define TI5 8
#define AST 80              // smem row stride bytes (64B data + 16 pad; 16-aligned)
#define BOFF 81920          // B region offset (1024 rows * 80)
#define STAGE 163840        // j-table stage offset
#define SMEM3 166912

typedef unsigned long long u64;
typedef uint32_t u32;

__device__ float g_Wh[Nn * CC];
__device__ u32   g_WhT[2][CC][Nn / 2];     // [plane][col][j-pair] bf16x2
__device__ float g_srcT[Nn * NH], g_dstT[Nn * NH];
__device__ float g_E1d[Nn * NH], g_E2d[Nn * NH];    // exp(dst), exp(.2 dst)
__device__ float g_E1sr[Nn * NH], g_E2sr[Nn * NH];  // exp(src), exp(.2 src)
__device__ float g_E1sz[Nn * NH], g_E2sz[Nn * NH];  // * zinv
__device__ float g_hp[JSPLIT][Nn * CC];
__device__ float g_Wh2[Nn * NC];
__device__ float4 g_s2e[Nn], g_d2e[Nn];

__device__ __forceinline__ void ffma2(u64& d, u64 a, u64 b) {
    asm("fma.rn.f32x2 %0, %1, %2, %0;" : "+l"(d) : "l"(a), "l"(b));
}
__device__ __forceinline__ float2 unpk(u64 v) {
    float2 r;
    asm("mov.b64 {%0, %1}, %2;" : "=f"(r.x), "=f"(r.y) : "l"(v));
    return r;
}
__device__ __forceinline__ u32 cvt2(float lo, float hi) {
    u32 r;
    asm("cvt.rn.bf16x2.f32 %0, %1, %2;" : "=r"(r) : "f"(hi), "f"(lo));
    return r;
}
__device__ __forceinline__ void ldsm4(u32& r0, u32& r1, u32& r2, u32& r3, u32 a) {
    asm volatile("ldmatrix.sync.aligned.m8n8.x4.shared.b16 {%0,%1,%2,%3}, [%4];"
                 : "=r"(r0), "=r"(r1), "=r"(r2), "=r"(r3) : "r"(a));
}
__device__ __forceinline__ void hmma(float* d, const u32* a, u32 b0, u32 b1) {
    asm volatile(
        "mma.sync.aligned.m16n8k16.row.col.f32.bf16.bf16.f32 "
        "{%0,%1,%2,%3}, {%4,%5,%6,%7}, {%8,%9}, {%0,%1,%2,%3};"
        : "+f"(d[0]), "+f"(d[1]), "+f"(d[2]), "+f"(d[3])
        : "r"(a[0]), "r"(a[1]), "r"(a[2]), "r"(a[3]), "r"(b0), "r"(b1));
}

// ========== K1: Wh = x @ W ; bf16 hi/lo split transpose to g_WhT ==========
__global__ void __launch_bounds__(256) k1_gemm(const float* __restrict__ x,
                                               const float* __restrict__ W) {
    __shared__ float As[16][64], Bs[16][64];
    int t = threadIdx.x, tx = t & 15, ty = t >> 4;
    int row0 = blockIdx.y * 64, col0 = blockIdx.x * 64;
    const float* Wb = W + (size_t)(col0 >> 6) * FIN * 64;
    int ra_r = t >> 2, ra_c = (t & 3) << 2, rb_r = t >> 4, rb_c = (t & 15) << 2;
    float4 ra = *(const float4*)&x[(size_t)(row0 + ra_r) * FIN + ra_c];
    float4 rb = *(const float4*)&Wb[(size_t)rb_r * 64 + rb_c];
    u64 acc[2][4];
#pragma unroll
    for (int i = 0; i < 2; i++)
#pragma unroll
        for (int j = 0; j < 4; j++) acc[i][j] = 0ull;
    for (int k0 = 0; k0 < FIN; k0 += 16) {
        As[ra_c][ra_r] = ra.x; As[ra_c + 1][ra_r] = ra.y;
        As[ra_c + 2][ra_r] = ra.z; As[ra_c + 3][ra_r] = ra.w;
        *(float4*)&Bs[rb_r][rb_c] = rb;
        __syncthreads();
        if (k0 + 16 < FIN) {
            ra = *(const float4*)&x[(size_t)(row0 + ra_r) * FIN + k0 + 16 + ra_c];
            rb = *(const float4*)&Wb[(size_t)(k0 + 16 + rb_r) * 64 + rb_c];
        }
#pragma unroll
        for (int k = 0; k < 16; k++) {
            ulonglong2 ap = *(const ulonglong2*)&As[k][ty * 4];
            float4 b4 = *(const float4*)&Bs[k][tx * 4];
            u64 bd[4];
            asm("mov.b64 %0, {%1, %1};" : "=l"(bd[0]) : "f"(b4.x));
            asm("mov.b64 %0, {%1, %1};" : "=l"(bd[1]) : "f"(b4.y));
            asm("mov.b64 %0, {%1, %1};" : "=l"(bd[2]) : "f"(b4.z));
            asm("mov.b64 %0, {%1, %1};" : "=l"(bd[3]) : "f"(b4.w));
#pragma unroll
            for (int c = 0; c < 4; c++) {
                ffma2(acc[0][c], ap.x, bd[c]);
                ffma2(acc[1][c], ap.y, bd[c]);
            }
        }
        __syncthreads();
    }
#pragma unroll
    for (int rp = 0; rp < 2; rp++) {
        float2 cv[4];
#pragma unroll
        for (int c = 0; c < 4; c++) cv[c] = unpk(acc[rp][c]);
        int r = row0 + ty * 4 + rp * 2;
        *(float4*)&g_Wh[(size_t)r * CC + col0 + tx * 4] =
            make_float4(cv[0].x, cv[1].x, cv[2].x, cv[3].x);
        *(float4*)&g_Wh[(size_t)(r + 1) * CC + col0 + tx * 4] =
            make_float4(cv[0].y, cv[1].y, cv[2].y, cv[3].y);
#pragma unroll
        for (int c = 0; c < 4; c++) {
            int gc = col0 + tx * 4 + c;
            u32 hp = cvt2(cv[c].x, cv[c].y);
            float hx = __uint_as_float(hp << 16);
            float hy = __uint_as_float(hp & 0xFFFF0000u);
            g_WhT[0][gc][r >> 1] = hp;
            g_WhT[1][gc][r >> 1] = cvt2(cv[c].x - hx, cv[c].y - hy);
        }
    }
}

// ========== K1b: src/dst projections ==========
__global__ void __launch_bounds__(256) k_srcdst(const float* __restrict__ a_src,
                                                const float* __restrict__ a_dst) {
    int n = blockIdx.x, h = threadIdx.x >> 5, lane = threadIdx.x & 31;
    const float* wh = g_Wh + (size_t)n * CC + h * 64;
    float w0 = wh[lane], w1 = wh[lane + 32];
    float s = w0 * a_src[h * 64 + lane] + w1 * a_src[h * 64 + lane + 32];
    float d = w0 * a_dst[h * 64 + lane] + w1 * a_dst[h * 64 + lane + 32];
#pragma unroll
    for (int o = 16; o; o >>= 1) {
        s += __shfl_down_sync(0xffffffffu, s, o);
        d += __shfl_down_sync(0xffffffffu, d, o);
    }
    if (!lane) { g_srcT[n * NH + h] = s; g_dstT[n * NH + h] = d; }
}

// ========== Ke: exp tables ==========
__global__ void __launch_bounds__(256) k_e() {
    int id = blockIdx.x * 256 + threadIdx.x;
    float s = g_srcT[id], d = g_dstT[id];
    g_E1sr[id] = __expf(s);
    g_E2sr[id] = __expf(LRA * s);
    g_E1d[id] = __expf(d);
    g_E2d[id] = __expf(LRA * d);
}

// ========== K2: Z via factorized selection; writes E1sz/E2sz ==========
__global__ void __launch_bounds__(256) k2_z(const int* __restrict__ adj) {
    extern __shared__ float s2m[];
    float* sd = s2m;
    float* sf1 = s2m + 5120;
    float* sf2 = s2m + 10240;
    int t = threadIdx.x, ti = t >> 4, sub = t & 15;
    int i = blockIdx.x * 16 + ti;
    float sv[8], a1[8], a2[8];
#pragma unroll
    for (int h = 0; h < 8; h++) {
        sv[h] = g_srcT[i * NH + h]; a1[h] = 0.f; a2[h] = 0.f;
    }
    for (int c0 = 0; c0 < Nn; c0 += 512) {
        __syncthreads();
#pragma unroll
        for (int q = 0; q < 16; q++) {
            int idx = q * 256 + t;
            int jj = idx >> 3, h = idx & 7;
            sd[jj * 10 + h] = g_dstT[(size_t)c0 * 8 + idx];
            sf1[jj * 10 + h] = g_E1d[(size_t)c0 * 8 + idx];
            sf2[jj * 10 + h] = g_E2d[(size_t)c0 * 8 + idx];
        }
        __syncthreads();
        for (int jj = 0; jj < 32; jj++) {
            int j = sub + jj * 16;
            bool m = adj[(size_t)i * Nn + c0 + j] > 0;
            const float* dp = &sd[j * 10];
            const float* p1 = &sf1[j * 10];
            const float* p2 = &sf2[j * 10];
#pragma unroll
            for (int h = 0; h < 8; h++) {
                bool c = (sv[h] + dp[h]) > 0.f;
                a1[h] += (m && c) ? p1[h] : 0.f;
                a2[h] += (m && !c) ? p2[h] : 0.f;
            }
        }
    }
#pragma unroll
    for (int h = 0; h < 8; h++) {
        float v1 = a1[h], v2 = a2[h];
#pragma unroll
        for (int o = 8; o; o >>= 1) {
            v1 += __shfl_down_sync(0xffffffffu, v1, o, 16);
            v2 += __shfl_down_sync(0xffffffffu, v2, o, 16);
        }
        a1[h] = v1; a2[h] = v2;
    }
    if (!sub) {
#pragma unroll
        for (int h = 0; h < 8; h++) {
            float e1 = g_E1sr[i * NH + h], e2 = g_E2sr[i * NH + h];
            float zi = 1.f / (e1 * a1[h] + e2 * a2[h]);
            g_E1sz[i * NH + h] = e1 * zi;
            g_E2sz[i * NH + h] = e2 * zi;
        }
    }
}

// ========== K3: pgen + avg + mma.sync bf16-split (att @ Wh) ==========
// smem: A planes [8h][2pl][64r][80B] @0 ; B planes [8h][2pl][64n][80B] @81920
//       j-stage 3x1KB @163840
__global__ void __launch_bounds__(512) k3_att(const int* __restrict__ adj,
                                              float* __restrict__ avg) {
    extern __shared__ char smc[];
    const u32 su = (u32)__cvta_generic_to_shared(smc);
    float* sd_s = (float*)(smc + STAGE);
    float* se1_s = sd_s + 256;
    float* se2_s = se1_s + 256;
    int t = threadIdx.x, lane = t & 31, w = t >> 5;
    int i0 = blockIdx.y * TI, jbase = blockIdx.x * JCHUNK;
    int rowg = w & 3, hp = w >> 2;
    int rp = t >> 3, jq = t & 7;

    // ldmatrix lane geometry
    int a_row = rowg * 16 + (lane & 15);
    int a_ko = ((lane >> 4) & 1) * 16;
    int b_n = (lane & 7) + ((lane >> 4) & 1) * 8;
    int b_ko = ((lane >> 3) & 1) * 16;

    float dacc[2][8][4];
#pragma unroll
    for (int a = 0; a < 2; a++)
#pragma unroll
        for (int b = 0; b < 8; b++)
#pragma unroll
            for (int c = 0; c < 4; c++) dacc[a][b][c] = 0.f;

    for (int jt = 0; jt < NT3; jt++) {
        int j0 = jbase + jt * TJ;
        // ---- B tile copy (g_WhT slice -> smem, ldmatrix-ready) ----
#pragma unroll
        for (int q = 0; q < 8; q++) {
            int idx = q * 512 + t;
            int row = idx >> 2, seg = idx & 3;
            int h = row >> 7, pl = (row >> 6) & 1, n = row & 63;
            uint4 v = *(const uint4*)((const char*)&g_WhT[pl][h * 64 + n][j0 >> 1] +
                                      seg * 16);
            *(uint4*)(smc + BOFF + row * AST + seg * 16) = v;
        }
        // ---- stage j tables ----
        if (t < 256) {
            sd_s[t] = g_dstT[(size_t)j0 * 8 + t];
            se1_s[t] = g_E1d[(size_t)j0 * 8 + t];
            se2_s[t] = g_E2d[(size_t)j0 * 8 + t];
        }
        __syncthreads();
        // ---- pgen: p -> bf16 hi/lo A planes + avg ----
        {
            float sv[8], e1z[8], e2z[8];
            {
                const float* sp = &g_srcT[(size_t)(i0 + rp) * 8];
                const float* ap = &g_E1sz[(size_t)(i0 + rp) * 8];
                const float* bp = &g_E2sz[(size_t)(i0 + rp) * 8];
#pragma unroll
                for (int h = 0; h < 8; h += 4) {
                    float4 a = *(const float4*)&sp[h];
                    float4 b = *(const float4*)&ap[h];
                    float4 c = *(const float4*)&bp[h];
                    sv[h] = a.x; sv[h + 1] = a.y; sv[h + 2] = a.z; sv[h + 3] = a.w;
                    e1z[h] = b.x; e1z[h + 1] = b.y; e1z[h + 2] = b.z; e1z[h + 3] = b.w;
                    e2z[h] = c.x; e2z[h + 1] = c.y; e2z[h + 2] = c.z; e2z[h + 3] = c.w;
                }
            }
            int4 a4 = *(const int4*)&adj[(size_t)(i0 + rp) * Nn + j0 + jq * 4];
            int am[4] = {a4.x, a4.y, a4.z, a4.w};
            float sums[4];
#pragma unroll
            for (int pr = 0; pr < 2; pr++) {
                float p0[8], p1[8];
#pragma unroll
                for (int sel = 0; sel < 2; sel++) {
                    int jl = jq * 4 + pr * 2 + sel;
                    float4 d0 = *(const float4*)&sd_s[jl * 8];
                    float4 d1 = *(const float4*)&sd_s[jl * 8 + 4];
                    float4 f0 = *(const float4*)&se1_s[jl * 8];
                    float4 f1 = *(const float4*)&se1_s[jl * 8 + 4];
                    float4 g0 = *(const float4*)&se2_s[jl * 8];
                    float4 g1 = *(const float4*)&se2_s[jl * 8 + 4];
                    float dd[8] = {d0.x, d0.y, d0.z, d0.w, d1.x, d1.y, d1.z, d1.w};
                    float q1[8] = {f0.x, f0.y, f0.z, f0.w, f1.x, f1.y, f1.z, f1.w};
                    float q2[8] = {g0.x, g0.y, g0.z, g0.w, g1.x, g1.y, g1.z, g1.w};
                    float msk = am[pr * 2 + sel] > 0 ? 1.f : 0.f;
                    float s = 0.f;
                    float* pp = sel ? p1 : p0;
#pragma unroll
                    for (int h = 0; h < 8; h++) {
                        bool c = (sv[h] + dd[h]) > 0.f;
                        float v = (c ? e1z[h] * q1[h] : e2z[h] * q2[h]) * msk;
                        pp[h] = v; s += v;
                    }
                    sums[pr * 2 + sel] = s * 0.125f;
                }
                int boff = rp * AST + jq * 8 + pr * 4;
#pragma unroll
                for (int h = 0; h < 8; h++) {
                    u32 qh = cvt2(p0[h], p1[h]);
                    float h0 = __uint_as_float(qh << 16);
                    float h1 = __uint_as_float(qh & 0xFFFF0000u);
                    u32 ql = cvt2(p0[h] - h0, p1[h] - h1);
                    *(u32*)(smc + (h * 2 + 0) * 64 * AST + boff) = qh;
                    *(u32*)(smc + (h * 2 + 1) * 64 * AST + boff) = ql;
                }
            }
            *(float4*)&avg[(size_t)(i0 + rp) * Nn + j0 + jq * 4] =
                make_float4(sums[0], sums[1], sums[2], sums[3]);
        }
        __syncthreads();
        // ---- GEMM: dacc += p(hi/lo) x wh(hi/lo), 3 terms ----
#pragma unroll
        for (int ks = 0; ks < 2; ks++) {
#pragma unroll
            for (int hh = 0; hh < 2; hh++) {
                int h = hp * 2 + hh;
                u32 ah[4], al[4], bfr[16];
                u32 aaH = su + (u32)(((h * 2 + 0) * 64 + a_row) * AST + ks * 32 + a_ko);
                u32 aaL = su + (u32)(((h * 2 + 1) * 64 + a_row) * AST + ks * 32 + a_ko);
                ldsm4(ah[0], ah[1], ah[2], ah[3], aaH);
                ldsm4(al[0], al[1], al[2], al[3], aaL);
#pragma unroll
                for (int cp = 0; cp < 4; cp++) {
                    u32 ba = su + (u32)(BOFF + ((h * 2 + 0) * 64 + cp * 16 + b_n) * AST +
                                        ks * 32 + b_ko);
                    ldsm4(bfr[cp * 4], bfr[cp * 4 + 1], bfr[cp * 4 + 2], bfr[cp * 4 + 3], ba);
                }
#pragma unroll
                for (int cg = 0; cg < 8; cg++) {
                    u32 b0 = bfr[(cg >> 1) * 4 + (cg & 1) * 2];
                    u32 b1 = bfr[(cg >> 1) * 4 + (cg & 1) * 2 + 1];
                    hmma(dacc[hh][cg], ah, b0, b1);
                    hmma(dacc[hh][cg], al, b0, b1);
                }
#pragma unroll
                for (int cp = 0; cp < 4; cp++) {
                    u32 ba = su + (u32)(BOFF + ((h * 2 + 1) * 64 + cp * 16 + b_n) * AST +
                                        ks * 32 + b_ko);
                    ldsm4(bfr[cp * 4], bfr[cp * 4 + 1], bfr[cp * 4 + 2], bfr[cp * 4 + 3], ba);
                }
#pragma unroll
                for (int cg = 0; cg < 8; cg++) {
                    u32 b0 = bfr[(cg >> 1) * 4 + (cg & 1) * 2];
                    u32 b1 = bfr[(cg >> 1) * 4 + (cg & 1) * 2 + 1];
                    hmma(dacc[hh][cg], ah, b0, b1);
                }
            }
        }
        __syncthreads();
    }
    // ---- epilogue: registers -> g_hp ----
    float* dst = g_hp[blockIdx.x];
    int erow = i0 + rowg * 16 + (lane >> 2);
#pragma unroll
    for (int hh = 0; hh < 2; hh++)
#pragma unroll
        for (int cg = 0; cg < 8; cg++) {
            int col = (hp * 2 + hh) * 64 + cg * 8 + (lane & 3) * 2;
            *(float2*)&dst[(size_t)erow * CC + col] =
                make_float2(dacc[hh][cg][0], dacc[hh][cg][1]);
            *(float2*)&dst[(size_t)(erow + 8) * CC + col] =
                make_float2(dacc[hh][cg][2], dacc[hh][cg][3]);
        }
}

// ========== K4: elu + Wh2 + src2/dst2 + exp tables ==========
__global__ void __launch_bounds__(128) k4_out(const float* __restrict__ Wout,
                                              const float* __restrict__ aos,
                                              const float* __restrict__ aod) {
    int w = threadIdx.x >> 5, lane = threadIdx.x & 31;
    int row = blockIdx.x * 4 + w;
    float acc[NC];
#pragma unroll
    for (int c = 0; c < NC; c++) acc[c] = 0.f;
#pragma unroll 4
    for (int m = 0; m < FIN / 32; m++) {
        int k = m * 32 + lane;
        float v = 0.f;
#pragma unroll
        for (int s = 0; s < JSPLIT; s++) v += g_hp[s][(size_t)row * CC + k];
        v = v > 0.f ? v : (__expf(v) - 1.f);
        const float4* wp = (const float4*)(Wout + (size_t)k * NC);
        float4 w0 = wp[0], w1 = wp[1], w2 = wp[2], w3 = wp[3];
        acc[0] += v * w0.x; acc[1] += v * w0.y; acc[2] += v * w0.z; acc[3] += v * w0.w;
        acc[4] += v * w1.x; acc[5] += v * w1.y; acc[6] += v * w1.z; acc[7] += v * w1.w;
        acc[8] += v * w2.x; acc[9] += v * w2.y; acc[10] += v * w2.z; acc[11] += v * w2.w;
        acc[12] += v * w3.x; acc[13] += v * w3.y; acc[14] += v * w3.z; acc[15] += v * w3.w;
    }
#pragma unroll
    for (int c = 0; c < NC; c++) {
        float v = acc[c];
#pragma unroll
        for (int o = 16; o; o >>= 1) v += __shfl_down_sync(0xffffffffu, v, o);
        acc[c] = v;
    }
    if (!lane) {
        float s = 0.f, d = 0.f;
#pragma unroll
        for (int c = 0; c < NC; c++) {
            g_Wh2[(size_t)row * NC + c] = acc[c];
            s += acc[c] * aos[c];
            d += acc[c] * aod[c];
        }
        g_s2e[row] = make_float4(s, __expf(s), __expf(LRA * s), 0.f);
        g_d2e[row] = make_float4(d, __expf(d), __expf(LRA * d), 0.f);
    }
}

// ========== K5: output attention + log_softmax ==========
__global__ void __launch_bounds__(256) k5_final(const int* __restrict__ adj,
                                                float* __restrict__ out) {
    extern __shared__ float sm5[];
    float* p = sm5;
    float* w2s = p + TI5 * Nn;
    float* red = w2s + 256 * 17;
    int i0 = blockIdx.x * TI5;
    int t = threadIdx.x, lane = t & 31, w = t >> 5;
    float zs[TI5], s2v[TI5], q1[TI5], q2[TI5];
#pragma unroll
    for (int i = 0; i < TI5; i++) {
        float4 e = g_s2e[i0 + i];
        zs[i] = 0.f; s2v[i] = e.x; q1[i] = e.y; q2[i] = e.z;
    }
    for (int j = t; j < Nn; j += 256) {
        float4 e = g_d2e[j];
#pragma unroll
        for (int i = 0; i < TI5; i++) {
            bool c = (s2v[i] + e.x) > 0.f;
            float pv = c ? q1[i] * e.y : q2[i] * e.z;
            pv = adj[(size_t)(i0 + i) * Nn + j] > 0 ? pv : 0.f;
            p[i * Nn + j] = pv;
            zs[i] += pv;
        }
    }
#pragma unroll
    for (int i = 0; i < TI5; i++) {
        float v = zs[i];
#pragma unroll
        for (int o = 16; o; o >>= 1) v += __shfl_down_sync(0xffffffffu, v, o);
        if (!lane) red[w * TI5 + i] = v;
    }
    __syncthreads();
    float Z = 0.f;
#pragma unroll
    for (int ww = 0; ww < 8; ww++) Z += red[ww * TI5 + w];
    float zinv = 1.f / Z;
    float acc[NC];
#pragma unroll
    for (int c = 0; c < NC; c++) acc[c] = 0.f;
    for (int j0 = 0; j0 < Nn; j0 += 256) {
        __syncthreads();
        {
            const float4* gw = (const float4*)&g_Wh2[(size_t)(j0 + t) * NC];
            float4 v0 = gw[0], v1 = gw[1], v2 = gw[2], v3 = gw[3];
            float* ds = &w2s[t * 17];
            ds[0] = v0.x; ds[1] = v0.y; ds[2] = v0.z; ds[3] = v0.w;
            ds[4] = v1.x; ds[5] = v1.y; ds[6] = v1.z; ds[7] = v1.w;
            ds[8] = v2.x; ds[9] = v2.y; ds[10] = v2.z; ds[11] = v2.w;
            ds[12] = v3.x; ds[13] = v3.y; ds[14] = v3.z; ds[15] = v3.w;
        }
        __syncthreads();
#pragma unroll
        for (int jj0 = 0; jj0 < 256; jj0 += 32) {
            int jj = jj0 + lane;
            float pv = p[w * Nn + j0 + jj];
            const float* wr = &w2s[jj * 17];
#pragma unroll
            for (int c = 0; c < NC; c++) acc[c] += pv * wr[c];
        }
    }
#pragma unroll
    for (int c = 0; c < NC; c++) {
        float v = acc[c];
#pragma unroll
        for (int o = 16; o; o >>= 1) v += __shfl_down_sync(0xffffffffu, v, o);
        acc[c] = v;
    }
    if (!lane) {
        float ho[NC], mx = -1e30f;
#pragma unroll
        for (int c = 0; c < NC; c++) { ho[c] = acc[c] * zinv; mx = fmaxf(mx, ho[c]); }
        float se = 0.f;
#pragma unroll
        for (int c = 0; c < NC; c++) se += __expf(ho[c] - mx);
        float lse = mx + __logf(se);
#pragma unroll
        for (int c = 0; c < NC; c++) out[(size_t)(i0 + w) * NC + c] = ho[c] - lse;
    }
}

// =======================================================================
extern "C" void kernel_launch(void* const* d_in, const int* in_sizes, int n_in,
                              void* d_out, int out_size) {
    const float* x = (const float*)d_in[0];
    const int* adj = (const int*)d_in[1];
    const float* Whd = (const float*)d_in[2];
    const float* a_src = (const float*)d_in[3];
    const float* a_dst = (const float*)d_in[4];
    const float* Wout = (const float*)d_in[5];
    const float* aos = (const float*)d_in[6];
    const float* aod = (const float*)d_in[7];
    float* out = (float*)d_out;
    float* avg = out + (size_t)Nn * NC;

    const int SMEM2 = 512 * 10 * 3 * 4;
    const int SMEM5 = (TI5 * Nn + 256 * 17 + 64) * 4;
    cudaFuncSetAttribute(k2_z, cudaFuncAttributeMaxDynamicSharedMemorySize, SMEM2);
    cudaFuncSetAttribute(k3_att, cudaFuncAttributeMaxDynamicSharedMemorySize, SMEM3);
    cudaFuncSetAttribute(k5_final, cudaFuncAttributeMaxDynamicSharedMemorySize, SMEM5);

    k1_gemm<<<dim3(CC / 64, Nn / 64), 256>>>(x, Whd);
    k_srcdst<<<Nn, 256>>>(a_src, a_dst);
    k_e<<<Nn * NH / 256, 256>>>();
    k2_z<<<Nn / 16, 256, SMEM2>>>(adj);
    k3_att<<<dim3(JSPLIT, Nn / TI), 512, SMEM3>>>(adj, avg);
    k4_out<<<Nn / 4, 128>>>(Wout, aos, aod);
    k5_final<<<Nn / TI5, 256, SMEM5>>>(adj, out);
}

// round 8
// speedup vs baseline: 1.3640x; 1.3640x over previous
#include <cuda_runtime.h>
#include <cstdint>

#define Nn   3072
#define FIN  512
#define NH   8
#define CC   512
#define NC   16
#define LRA  0.2f
#define JSPLIT 3
#define JCHUNK 1024
#define TI   64
#define TJ   32
#define KSP  516     // p_s per-j stride in floats (129 float4s -> conflict-free)
#define HS   64
#define TI5  8

typedef unsigned long long u64;
typedef uint32_t u32;

// ---- static device scratch ----
__device__ float g_Wh[Nn * CC];
__device__ float g_srcT[Nn * NH], g_dstT[Nn * NH];
__device__ float g_E1d[Nn * NH], g_E2d[Nn * NH];    // exp(dst), exp(.2 dst)
__device__ float g_E1sz[Nn * NH], g_E2sz[Nn * NH];  // exp(src)/Z, exp(.2 src)/Z
__device__ float g_hp[JSPLIT][Nn * CC];
__device__ float g_Wh2[Nn * NC];
__device__ float4 g_s2e[Nn], g_d2e[Nn];

__device__ __forceinline__ float lrelu(float x) { return fmaxf(x, LRA * x); }
__device__ __forceinline__ void ffma2(u64& d, u64 a, u64 b) {
    asm("fma.rn.f32x2 %0, %1, %2, %0;" : "+l"(d) : "l"(a), "l"(b));
}
__device__ __forceinline__ float2 unpk(u64 v) {
    float2 r;
    asm("mov.b64 {%0, %1}, %2;" : "=f"(r.x), "=f"(r.y) : "l"(v));
    return r;
}

// ================= K1: Wh = x @ W (64x64 tile SGEMM, f32x2, pipelined) =====
__global__ void __launch_bounds__(256) k1_gemm(const float* __restrict__ x,
                                               const float* __restrict__ W) {
    __shared__ float As[16][64], Bs[16][64];
    int t = threadIdx.x, tx = t & 15, ty = t >> 4;
    int row0 = blockIdx.y * 64, col0 = blockIdx.x * 64;
    const float* Wb = W + (size_t)(col0 >> 6) * FIN * 64;
    int ra_r = t >> 2, ra_c = (t & 3) << 2, rb_r = t >> 4, rb_c = (t & 15) << 2;
    float4 ra = *(const float4*)&x[(size_t)(row0 + ra_r) * FIN + ra_c];
    float4 rb = *(const float4*)&Wb[(size_t)rb_r * 64 + rb_c];
    u64 acc[2][4];
#pragma unroll
    for (int i = 0; i < 2; i++)
#pragma unroll
        for (int j = 0; j < 4; j++) acc[i][j] = 0ull;
    for (int k0 = 0; k0 < FIN; k0 += 16) {
        As[ra_c][ra_r] = ra.x; As[ra_c + 1][ra_r] = ra.y;
        As[ra_c + 2][ra_r] = ra.z; As[ra_c + 3][ra_r] = ra.w;
        *(float4*)&Bs[rb_r][rb_c] = rb;
        __syncthreads();
        if (k0 + 16 < FIN) {
            ra = *(const float4*)&x[(size_t)(row0 + ra_r) * FIN + k0 + 16 + ra_c];
            rb = *(const float4*)&Wb[(size_t)(k0 + 16 + rb_r) * 64 + rb_c];
        }
#pragma unroll
        for (int k = 0; k < 16; k++) {
            ulonglong2 ap = *(const ulonglong2*)&As[k][ty * 4];
            float4 b4 = *(const float4*)&Bs[k][tx * 4];
            u64 bd[4];
            asm("mov.b64 %0, {%1, %1};" : "=l"(bd[0]) : "f"(b4.x));
            asm("mov.b64 %0, {%1, %1};" : "=l"(bd[1]) : "f"(b4.y));
            asm("mov.b64 %0, {%1, %1};" : "=l"(bd[2]) : "f"(b4.z));
            asm("mov.b64 %0, {%1, %1};" : "=l"(bd[3]) : "f"(b4.w));
#pragma unroll
            for (int c = 0; c < 4; c++) {
                ffma2(acc[0][c], ap.x, bd[c]);
                ffma2(acc[1][c], ap.y, bd[c]);
            }
        }
        __syncthreads();
    }
#pragma unroll
    for (int rp = 0; rp < 2; rp++) {
        float2 c0 = unpk(acc[rp][0]), c1 = unpk(acc[rp][1]);
        float2 c2 = unpk(acc[rp][2]), c3 = unpk(acc[rp][3]);
        int r = row0 + ty * 4 + rp * 2;
        *(float4*)&g_Wh[(size_t)r * CC + col0 + tx * 4] =
            make_float4(c0.x, c1.x, c2.x, c3.x);
        *(float4*)&g_Wh[(size_t)(r + 1) * CC + col0 + tx * 4] =
            make_float4(c0.y, c1.y, c2.y, c3.y);
    }
}

// ================= K1b: src/dst projections =================
__global__ void __launch_bounds__(256) k_srcdst(const float* __restrict__ a_src,
                                                const float* __restrict__ a_dst) {
    int n = blockIdx.x, h = threadIdx.x >> 5, lane = threadIdx.x & 31;
    const float* wh = g_Wh + (size_t)n * CC + h * 64;
    float w0 = wh[lane], w1 = wh[lane + 32];
    float s = w0 * a_src[h * 64 + lane] + w1 * a_src[h * 64 + lane + 32];
    float d = w0 * a_dst[h * 64 + lane] + w1 * a_dst[h * 64 + lane + 32];
#pragma unroll
    for (int o = 16; o; o >>= 1) {
        s += __shfl_down_sync(0xffffffffu, s, o);
        d += __shfl_down_sync(0xffffffffu, d, o);
    }
    if (!lane) { g_srcT[n * NH + h] = s; g_dstT[n * NH + h] = d; }
}

// ================= Ke: dst exp tables =================
__global__ void __launch_bounds__(256) k_e() {
    int id = blockIdx.x * 256 + threadIdx.x;
    float d = g_dstT[id];
    g_E1d[id] = __expf(d);
    g_E2d[id] = __expf(LRA * d);
}

// ================= K2: Z ; writes E1sz/E2sz =================
__global__ void __launch_bounds__(256) k2_z(const int* __restrict__ adj) {
    int i = blockIdx.x;
    float sr[NH], sum[NH];
#pragma unroll
    for (int h = 0; h < NH; h++) { sr[h] = g_srcT[i * NH + h]; sum[h] = 0.f; }
    const int* arow = adj + (size_t)i * Nn;
    for (int j = threadIdx.x; j < Nn; j += 256) {
        if (arow[j] > 0) {
            const float4* dp = (const float4*)(g_dstT + (size_t)j * NH);
            float4 d0 = dp[0], d1 = dp[1];
            float dv[8] = {d0.x, d0.y, d0.z, d0.w, d1.x, d1.y, d1.z, d1.w};
#pragma unroll
            for (int h = 0; h < NH; h++) sum[h] += __expf(lrelu(sr[h] + dv[h]));
        }
    }
    __shared__ float red[8][NH];
    int lane = threadIdx.x & 31, w = threadIdx.x >> 5;
#pragma unroll
    for (int h = 0; h < NH; h++) {
        float v = sum[h];
#pragma unroll
        for (int o = 16; o; o >>= 1) v += __shfl_down_sync(0xffffffffu, v, o);
        if (!lane) red[w][h] = v;
    }
    __syncthreads();
    if (threadIdx.x < NH) {
        float v = 0.f;
#pragma unroll
        for (int ww = 0; ww < 8; ww++) v += red[ww][threadIdx.x];
        float zi = 1.f / v;
        float s = g_srcT[i * NH + threadIdx.x];
        g_E1sz[i * NH + threadIdx.x] = __expf(s) * zi;
        g_E2sz[i * NH + threadIdx.x] = __expf(LRA * s) * zi;
    }
}

// ====== K3: fused exp-free p-gen + avg write + FFMA2 (att @ Wh) ======
// smem floats: wh_s 16384 | p_s 16512 | src_s 512 | e1z_s 512 | e2z_s 512
//              dst_b 2x256 | e1d_b 2x256 | e2d_b 2x256     (35968 total)
__global__ void __launch_bounds__(512) k3_att(const int* __restrict__ adj,
                                              float* __restrict__ avg) {
    extern __shared__ float sm[];
    float* wh_s  = sm;
    float* p_s   = sm + 16384;
    float* src_s = sm + 32896;   // [h][64]
    float* e1z_s = sm + 33408;
    float* e2z_s = sm + 33920;
    float* dst_b = sm + 34432;   // [2][8][32]
    float* e1d_b = sm + 34944;
    float* e2d_b = sm + 35456;

    int t = threadIdx.x;
    int i0 = blockIdx.y * TI;
    int jbase = blockIdx.x * JCHUNK;
    {   // transposed [h][r] fills (broadcast-friendly in pgen)
        int row = t >> 3, h = t & 7;
        src_s[h * 64 + row] = g_srcT[i0 * NH + t];
        e1z_s[h * 64 + row] = g_E1sz[i0 * NH + t];
        e2z_s[h * 64 + row] = g_E2sz[i0 * NH + t];
    }
    int tc = t & 127, tr = t >> 7;
    int lane = t & 31, w = t >> 5;
    int r0p = w * 4;
    int r0g = tr * 16;
    int hg = tc >> 4;
    int col0 = tc * 4;
    int th = t >> 5, tk = t & 31;   // table-load ids (t<256)

    if (t < 256) {   // prologue: tables for tile 0 into buf 0
        dst_b[th * 32 + tk] = g_dstT[(size_t)(jbase + tk) * NH + th];
        e1d_b[th * 32 + tk] = g_E1d[(size_t)(jbase + tk) * NH + th];
        e2d_b[th * 32 + tk] = g_E2d[(size_t)(jbase + tk) * NH + th];
    }
    u64 acc[8][4];
#pragma unroll
    for (int a = 0; a < 8; a++)
#pragma unroll
        for (int c = 0; c < 4; c++) acc[a][c] = 0ull;
    __syncthreads();

    for (int jt = 0; jt < JCHUNK / TJ; jt++) {
        int bsel = jt & 1;
        int j0 = jbase + jt * TJ;
        // ---- phase A: wh load + next tables + pgen (p_s write) ----
#pragma unroll
        for (int q = 0; q < 8; q++) {
            int idx = q * 512 + t;
            int jj = idx >> 7, c4 = (idx & 127) << 2;
            *(float4*)&wh_s[jj * CC + c4] =
                *(const float4*)&g_Wh[(size_t)(j0 + jj) * CC + c4];
        }
        if (jt + 1 < JCHUNK / TJ && t < 256) {
            int j1 = j0 + TJ, nb = 1 - bsel;
            dst_b[nb * 256 + th * 32 + tk] = g_dstT[(size_t)(j1 + tk) * NH + th];
            e1d_b[nb * 256 + th * 32 + tk] = g_E1d[(size_t)(j1 + tk) * NH + th];
            e2d_b[nb * 256 + th * 32 + tk] = g_E2d[(size_t)(j1 + tk) * NH + th];
        }
        {   // pgen: warp w owns rows r0p..r0p+3, lane = j-in-tile
            const int* arow = &adj[(size_t)(i0 + r0p) * Nn + j0 + lane];
            float msk0 = arow[0] > 0 ? 1.f : 0.f;
            float msk1 = arow[Nn] > 0 ? 1.f : 0.f;
            float msk2 = arow[2 * Nn] > 0 ? 1.f : 0.f;
            float msk3 = arow[3 * Nn] > 0 ? 1.f : 0.f;
            float sumv[4] = {0.f, 0.f, 0.f, 0.f};
            const float* db = dst_b + bsel * 256;
            const float* f1 = e1d_b + bsel * 256;
            const float* f2 = e2d_b + bsel * 256;
#pragma unroll
            for (int m = 0; m < 4; m++) {
                int h0 = 2 * m;
                float d0 = db[h0 * 32 + lane], d1 = db[h0 * 32 + 32 + lane];
                float q10 = f1[h0 * 32 + lane], q11 = f1[h0 * 32 + 32 + lane];
                float q20 = f2[h0 * 32 + lane], q21 = f2[h0 * 32 + 32 + lane];
                float4 s0 = *(const float4*)&src_s[h0 * 64 + r0p];
                float4 s1 = *(const float4*)&src_s[(h0 + 1) * 64 + r0p];
                float4 a0 = *(const float4*)&e1z_s[h0 * 64 + r0p];
                float4 a1 = *(const float4*)&e1z_s[(h0 + 1) * 64 + r0p];
                float4 b0 = *(const float4*)&e2z_s[h0 * 64 + r0p];
                float4 b1 = *(const float4*)&e2z_s[(h0 + 1) * 64 + r0p];
                float4 v0, v1;
                v0.x = ((s0.x + d0 > 0.f) ? a0.x * q10 : b0.x * q20) * msk0;
                v0.y = ((s0.y + d0 > 0.f) ? a0.y * q10 : b0.y * q20) * msk1;
                v0.z = ((s0.z + d0 > 0.f) ? a0.z * q10 : b0.z * q20) * msk2;
                v0.w = ((s0.w + d0 > 0.f) ? a0.w * q10 : b0.w * q20) * msk3;
                v1.x = ((s1.x + d1 > 0.f) ? a1.x * q11 : b1.x * q21) * msk0;
                v1.y = ((s1.y + d1 > 0.f) ? a1.y * q11 : b1.y * q21) * msk1;
                v1.z = ((s1.z + d1 > 0.f) ? a1.z * q11 : b1.z * q21) * msk2;
                v1.w = ((s1.w + d1 > 0.f) ? a1.w * q11 : b1.w * q21) * msk3;
                sumv[0] += v0.x + v1.x; sumv[1] += v0.y + v1.y;
                sumv[2] += v0.z + v1.z; sumv[3] += v0.w + v1.w;
                *(float4*)&p_s[lane * KSP + h0 * HS + r0p] = v0;
                *(float4*)&p_s[lane * KSP + (h0 + 1) * HS + r0p] = v1;
            }
#pragma unroll
            for (int rr = 0; rr < 4; rr++)
                avg[(size_t)(i0 + r0p + rr) * Nn + j0 + lane] =
                    sumv[rr] * 0.125f;
        }
        __syncthreads();
        // ---- GEMM: acc[16 rows x 4 cols] += p^T * wh ----
#pragma unroll 4
        for (int k = 0; k < TJ; k++) {
            const float* pb = &p_s[k * KSP + hg * HS + r0g];
            ulonglong2 a01 = *(const ulonglong2*)(pb);
            ulonglong2 a23 = *(const ulonglong2*)(pb + 4);
            ulonglong2 a45 = *(const ulonglong2*)(pb + 8);
            ulonglong2 a67 = *(const ulonglong2*)(pb + 12);
            float4 b4 = *(const float4*)&wh_s[k * CC + col0];
            u64 bd[4];
            asm("mov.b64 %0, {%1, %1};" : "=l"(bd[0]) : "f"(b4.x));
            asm("mov.b64 %0, {%1, %1};" : "=l"(bd[1]) : "f"(b4.y));
            asm("mov.b64 %0, {%1, %1};" : "=l"(bd[2]) : "f"(b4.z));
            asm("mov.b64 %0, {%1, %1};" : "=l"(bd[3]) : "f"(b4.w));
#pragma unroll
            for (int c = 0; c < 4; c++) {
                ffma2(acc[0][c], a01.x, bd[c]);
                ffma2(acc[1][c], a01.y, bd[c]);
                ffma2(acc[2][c], a23.x, bd[c]);
                ffma2(acc[3][c], a23.y, bd[c]);
                ffma2(acc[4][c], a45.x, bd[c]);
                ffma2(acc[5][c], a45.y, bd[c]);
                ffma2(acc[6][c], a67.x, bd[c]);
                ffma2(acc[7][c], a67.y, bd[c]);
            }
        }
        __syncthreads();
    }
    float* dst = g_hp[blockIdx.x];
#pragma unroll
    for (int rp = 0; rp < 8; rp++) {
        float2 c0 = unpk(acc[rp][0]), c1 = unpk(acc[rp][1]);
        float2 c2 = unpk(acc[rp][2]), c3 = unpk(acc[rp][3]);
        int r = i0 + r0g + rp * 2;
        *(float4*)&dst[(size_t)r * CC + col0] = make_float4(c0.x, c1.x, c2.x, c3.x);
        *(float4*)&dst[(size_t)(r + 1) * CC + col0] = make_float4(c0.y, c1.y, c2.y, c3.y);
    }
}

// ========== K4: elu + Wh2 + src2/dst2 exp tables ==========
__global__ void __launch_bounds__(128) k4_out(const float* __restrict__ Wout,
                                              const float* __restrict__ aos,
                                              const float* __restrict__ aod) {
    int w = threadIdx.x >> 5, lane = threadIdx.x & 31;
    int row = blockIdx.x * 4 + w;
    float acc[NC];
#pragma unroll
    for (int c = 0; c < NC; c++) acc[c] = 0.f;
#pragma unroll 4
    for (int m = 0; m < FIN / 32; m++) {
        int k = m * 32 + lane;
        float v = 0.f;
#pragma unroll
        for (int s = 0; s < JSPLIT; s++) v += g_hp[s][(size_t)row * CC + k];
        v = v > 0.f ? v : (__expf(v) - 1.f);
        const float4* wp = (const float4*)(Wout + (size_t)k * NC);
        float4 w0 = wp[0], w1 = wp[1], w2 = wp[2], w3 = wp[3];
        acc[0] += v * w0.x; acc[1] += v * w0.y; acc[2] += v * w0.z; acc[3] += v * w0.w;
        acc[4] += v * w1.x; acc[5] += v * w1.y; acc[6] += v * w1.z; acc[7] += v * w1.w;
        acc[8] += v * w2.x; acc[9] += v * w2.y; acc[10] += v * w2.z; acc[11] += v * w2.w;
        acc[12] += v * w3.x; acc[13] += v * w3.y; acc[14] += v * w3.z; acc[15] += v * w3.w;
    }
#pragma unroll
    for (int c = 0; c < NC; c++) {
        float v = acc[c];
#pragma unroll
        for (int o = 16; o; o >>= 1) v += __shfl_down_sync(0xffffffffu, v, o);
        acc[c] = v;
    }
    if (!lane) {
        float s = 0.f, d = 0.f;
#pragma unroll
        for (int c = 0; c < NC; c++) {
            g_Wh2[(size_t)row * NC + c] = acc[c];
            s += acc[c] * aos[c];
            d += acc[c] * aod[c];
        }
        g_s2e[row] = make_float4(s, __expf(s), __expf(LRA * s), 0.f);
        g_d2e[row] = make_float4(d, __expf(d), __expf(LRA * d), 0.f);
    }
}

// ========== K5: output attention + log_softmax ==========
__global__ void __launch_bounds__(256) k5_final(const int* __restrict__ adj,
                                                float* __restrict__ out) {
    extern __shared__ float sm5[];
    float* p = sm5;
    float* w2s = p + TI5 * Nn;
    float* red = w2s + 256 * 17;
    int i0 = blockIdx.x * TI5;
    int t = threadIdx.x, lane = t & 31, w = t >> 5;
    float zs[TI5], s2v[TI5], q1[TI5], q2[TI5];
#pragma unroll
    for (int i = 0; i < TI5; i++) {
        float4 e = g_s2e[i0 + i];
        zs[i] = 0.f; s2v[i] = e.x; q1[i] = e.y; q2[i] = e.z;
    }
    for (int j = t; j < Nn; j += 256) {
        float4 e = g_d2e[j];
#pragma unroll
        for (int i = 0; i < TI5; i++) {
            bool c = (s2v[i] + e.x) > 0.f;
            float pv = c ? q1[i] * e.y : q2[i] * e.z;
            pv = adj[(size_t)(i0 + i) * Nn + j] > 0 ? pv : 0.f;
            p[i * Nn + j] = pv;
            zs[i] += pv;
        }
    }
#pragma unroll
    for (int i = 0; i < TI5; i++) {
        float v = zs[i];
#pragma unroll
        for (int o = 16; o; o >>= 1) v += __shfl_down_sync(0xffffffffu, v, o);
        if (!lane) red[w * TI5 + i] = v;
    }
    __syncthreads();
    float Z = 0.f;
#pragma unroll
    for (int ww = 0; ww < 8; ww++) Z += red[ww * TI5 + w];
    float zinv = 1.f / Z;
    float acc[NC];
#pragma unroll
    for (int c = 0; c < NC; c++) acc[c] = 0.f;
    for (int j0 = 0; j0 < Nn; j0 += 256) {
        __syncthreads();
        {
            const float4* gw = (const float4*)&g_Wh2[(size_t)(j0 + t) * NC];
            float4 v0 = gw[0], v1 = gw[1], v2 = gw[2], v3 = gw[3];
            float* ds = &w2s[t * 17];
            ds[0] = v0.x; ds[1] = v0.y; ds[2] = v0.z; ds[3] = v0.w;
            ds[4] = v1.x; ds[5] = v1.y; ds[6] = v1.z; ds[7] = v1.w;
            ds[8] = v2.x; ds[9] = v2.y; ds[10] = v2.z; ds[11] = v2.w;
            ds[12] = v3.x; ds[13] = v3.y; ds[14] = v3.z; ds[15] = v3.w;
        }
        __syncthreads();
#pragma unroll
        for (int jj0 = 0; jj0 < 256; jj0 += 32) {
            int jj = jj0 + lane;
            float pv = p[w * Nn + j0 + jj];
            const float* wr = &w2s[jj * 17];
#pragma unroll
            for (int c = 0; c < NC; c++) acc[c] += pv * wr[c];
        }
    }
#pragma unroll
    for (int c = 0; c < NC; c++) {
        float v = acc[c];
#pragma unroll
        for (int o = 16; o; o >>= 1) v += __shfl_down_sync(0xffffffffu, v, o);
        acc[c] = v;
    }
    if (!lane) {
        float ho[NC], mx = -1e30f;
#pragma unroll
        for (int c = 0; c < NC; c++) { ho[c] = acc[c] * zinv; mx = fmaxf(mx, ho[c]); }
        float se = 0.f;
#pragma unroll
        for (int c = 0; c < NC; c++) se += __expf(ho[c] - mx);
        float lse = mx + __logf(se);
#pragma unroll
        for (int c = 0; c < NC; c++) out[(size_t)(i0 + w) * NC + c] = ho[c] - lse;
    }
}

// =======================================================================
extern "C" void kernel_launch(void* const* d_in, const int* in_sizes, int n_in,
                              void* d_out, int out_size) {
    const float* x = (const float*)d_in[0];
    const int* adj = (const int*)d_in[1];
    const float* Whd = (const float*)d_in[2];
    const float* a_src = (const float*)d_in[3];
    const float* a_dst = (const float*)d_in[4];
    const float* Wout = (const float*)d_in[5];
    const float* aos = (const float*)d_in[6];
    const float* aod = (const float*)d_in[7];
    float* out = (float*)d_out;
    float* avg = out + (size_t)Nn * NC;

    const int SMEM3 = 35968 * 4;                 // 143,872 B
    const int SMEM5 = (TI5 * Nn + 256 * 17 + 64) * 4;
    cudaFuncSetAttribute(k3_att, cudaFuncAttributeMaxDynamicSharedMemorySize, SMEM3);
    cudaFuncSetAttribute(k5_final, cudaFuncAttributeMaxDynamicSharedMemorySize, SMEM5);

    k1_gemm<<<dim3(CC / 64, Nn / 64), 256>>>(x, Whd);
    k_srcdst<<<Nn, 256>>>(a_src, a_dst);
    k_e<<<Nn * NH / 256, 256>>>();
    k2_z<<<Nn, 256>>>(adj);
    k3_att<<<dim3(JSPLIT, Nn / TI), 512, SMEM3>>>(adj, avg);
    k4_out<<<Nn / 4, 128>>>(Wout, aos, aod);
    k5_final<<<Nn / TI5, 256, SMEM5>>>(adj, out);
}

// round 9
// speedup vs baseline: 1.4423x; 1.0574x over previous
#include <cuda_runtime.h>
#include <cstdint>

#define Nn   3072
#define FIN  512
#define NH   8
#define CC   512
#define NC   16
#define LRA  0.2f
#define JSPLIT 3
#define JCHUNK 1024
#define TI   64
#define TJ   32
#define NT3  32      // JCHUNK/TJ
#define KSP  516     // p_s per-j stride in floats (129 float4s -> conflict-free)
#define HS   64
#define WB   16384   // wh_s buffer stride (floats)
#define TI5  8

typedef unsigned long long u64;
typedef uint32_t u32;

// ---- static device scratch ----
__device__ float g_Wh[Nn * CC];
__device__ float g_srcT[Nn * NH], g_dstT[Nn * NH], g_Zinv[Nn * NH];
__device__ float g_hp[JSPLIT][Nn * CC];
__device__ float g_Wh2[Nn * NC];
__device__ float4 g_s2e[Nn], g_d2e[Nn];

__device__ __forceinline__ float lrelu(float x) { return fmaxf(x, LRA * x); }
__device__ __forceinline__ void ffma2(u64& d, u64 a, u64 b) {
    asm("fma.rn.f32x2 %0, %1, %2, %0;" : "+l"(d) : "l"(a), "l"(b));
}
__device__ __forceinline__ float2 unpk(u64 v) {
    float2 r;
    asm("mov.b64 {%0, %1}, %2;" : "=f"(r.x), "=f"(r.y) : "l"(v));
    return r;
}
__device__ __forceinline__ void cp16(u32 s, const void* g) {
    asm volatile("cp.async.cg.shared.global [%0], [%1], 16;" :: "r"(s), "l"(g));
}
__device__ __forceinline__ void cp_commit() {
    asm volatile("cp.async.commit_group;" ::: "memory");
}
__device__ __forceinline__ void cp_waitall() {
    asm volatile("cp.async.wait_group 0;" ::: "memory");
}

// ================= K1: Wh = x @ W (64x64 tile SGEMM, f32x2, pipelined) =====
__global__ void __launch_bounds__(256) k1_gemm(const float* __restrict__ x,
                                               const float* __restrict__ W) {
    __shared__ float As[16][64], Bs[16][64];
    int t = threadIdx.x, tx = t & 15, ty = t >> 4;
    int row0 = blockIdx.y * 64, col0 = blockIdx.x * 64;
    const float* Wb = W + (size_t)(col0 >> 6) * FIN * 64;
    int ra_r = t >> 2, ra_c = (t & 3) << 2, rb_r = t >> 4, rb_c = (t & 15) << 2;
    float4 ra = *(const float4*)&x[(size_t)(row0 + ra_r) * FIN + ra_c];
    float4 rb = *(const float4*)&Wb[(size_t)rb_r * 64 + rb_c];
    u64 acc[2][4];
#pragma unroll
    for (int i = 0; i < 2; i++)
#pragma unroll
        for (int j = 0; j < 4; j++) acc[i][j] = 0ull;
    for (int k0 = 0; k0 < FIN; k0 += 16) {
        As[ra_c][ra_r] = ra.x; As[ra_c + 1][ra_r] = ra.y;
        As[ra_c + 2][ra_r] = ra.z; As[ra_c + 3][ra_r] = ra.w;
        *(float4*)&Bs[rb_r][rb_c] = rb;
        __syncthreads();
        if (k0 + 16 < FIN) {
            ra = *(const float4*)&x[(size_t)(row0 + ra_r) * FIN + k0 + 16 + ra_c];
            rb = *(const float4*)&Wb[(size_t)(k0 + 16 + rb_r) * 64 + rb_c];
        }
#pragma unroll
        for (int k = 0; k < 16; k++) {
            ulonglong2 ap = *(const ulonglong2*)&As[k][ty * 4];
            float4 b4 = *(const float4*)&Bs[k][tx * 4];
            u64 bd[4];
            asm("mov.b64 %0, {%1, %1};" : "=l"(bd[0]) : "f"(b4.x));
            asm("mov.b64 %0, {%1, %1};" : "=l"(bd[1]) : "f"(b4.y));
            asm("mov.b64 %0, {%1, %1};" : "=l"(bd[2]) : "f"(b4.z));
            asm("mov.b64 %0, {%1, %1};" : "=l"(bd[3]) : "f"(b4.w));
#pragma unroll
            for (int c = 0; c < 4; c++) {
                ffma2(acc[0][c], ap.x, bd[c]);
                ffma2(acc[1][c], ap.y, bd[c]);
            }
        }
        __syncthreads();
    }
#pragma unroll
    for (int rp = 0; rp < 2; rp++) {
        float2 c0 = unpk(acc[rp][0]), c1 = unpk(acc[rp][1]);
        float2 c2 = unpk(acc[rp][2]), c3 = unpk(acc[rp][3]);
        int r = row0 + ty * 4 + rp * 2;
        *(float4*)&g_Wh[(size_t)r * CC + col0 + tx * 4] =
            make_float4(c0.x, c1.x, c2.x, c3.x);
        *(float4*)&g_Wh[(size_t)(r + 1) * CC + col0 + tx * 4] =
            make_float4(c0.y, c1.y, c2.y, c3.y);
    }
}

// ================= K1b: src/dst projections =================
__global__ void __launch_bounds__(256) k_srcdst(const float* __restrict__ a_src,
                                                const float* __restrict__ a_dst) {
    int n = blockIdx.x, h = threadIdx.x >> 5, lane = threadIdx.x & 31;
    const float* wh = g_Wh + (size_t)n * CC + h * 64;
    float w0 = wh[lane], w1 = wh[lane + 32];
    float s = w0 * a_src[h * 64 + lane] + w1 * a_src[h * 64 + lane + 32];
    float d = w0 * a_dst[h * 64 + lane] + w1 * a_dst[h * 64 + lane + 32];
#pragma unroll
    for (int o = 16; o; o >>= 1) {
        s += __shfl_down_sync(0xffffffffu, s, o);
        d += __shfl_down_sync(0xffffffffu, d, o);
    }
    if (!lane) { g_srcT[n * NH + h] = s; g_dstT[n * NH + h] = d; }
}

// ================= K2: softmax denominators Z[h,i] =================
__global__ void __launch_bounds__(256) k2_z(const int* __restrict__ adj) {
    int i = blockIdx.x;
    float sr[NH], sum[NH];
#pragma unroll
    for (int h = 0; h < NH; h++) { sr[h] = g_srcT[i * NH + h]; sum[h] = 0.f; }
    const int* arow = adj + (size_t)i * Nn;
    for (int j = threadIdx.x; j < Nn; j += 256) {
        if (arow[j] > 0) {
            const float4* dp = (const float4*)(g_dstT + (size_t)j * NH);
            float4 d0 = dp[0], d1 = dp[1];
            float dv[8] = {d0.x, d0.y, d0.z, d0.w, d1.x, d1.y, d1.z, d1.w};
#pragma unroll
            for (int h = 0; h < NH; h++) sum[h] += __expf(lrelu(sr[h] + dv[h]));
        }
    }
    __shared__ float red[8][NH];
    int lane = threadIdx.x & 31, w = threadIdx.x >> 5;
#pragma unroll
    for (int h = 0; h < NH; h++) {
        float v = sum[h];
#pragma unroll
        for (int o = 16; o; o >>= 1) v += __shfl_down_sync(0xffffffffu, v, o);
        if (!lane) red[w][h] = v;
    }
    __syncthreads();
    if (threadIdx.x < NH) {
        float v = 0.f;
#pragma unroll
        for (int ww = 0; ww < 8; ww++) v += red[ww][threadIdx.x];
        g_Zinv[i * NH + threadIdx.x] = 1.f / v;
    }
}

// ====== K3: fused pgen + avg write + FFMA2 (att @ Wh), full cp.async ======
// smem floats: wh_s 2x16384 [0,32768) | p_s [32768,49280) | src_s [49280,49792)
//              zinv_s [49792,50304) | dst_b 2x256 [50304,50816)
//              adj_b 2x2048 ints [50816,54912)
__global__ void __launch_bounds__(512) k3_att(const int* __restrict__ adj,
                                              float* __restrict__ avg) {
    extern __shared__ float sm[];
    float* wh_s   = sm;
    float* p_s    = sm + 32768;
    float* src_s  = sm + 49280;
    float* zinv_s = sm + 49792;
    float* dst_b  = sm + 50304;
    int*   adj_b  = (int*)(sm + 50816);

    int t = threadIdx.x;
    int i0 = blockIdx.y * TI;
    int jbase = blockIdx.x * JCHUNK;

    // transposed [h][r] fills
    src_s[(t & 7) * TI + (t >> 3)]  = g_srcT[i0 * NH + t];
    zinv_s[(t & 7) * TI + (t >> 3)] = g_Zinv[i0 * NH + t];

    int tc = t & 127, tr = t >> 7;
    int lane = t & 31, w = t >> 5;
    int r0p = w * 4;
    int r0g = tr * 16;
    int hg = tc >> 4;
    int col0 = tc * 4;

    u32 whs_u  = (u32)__cvta_generic_to_shared(wh_s);
    u32 adjb_u = (u32)__cvta_generic_to_shared(adj_b);
    u32 dstb_u = (u32)__cvta_generic_to_shared(dst_b);
    int cp_row = t >> 3, cp_seg = (t & 7) << 2;

    auto issue_tile = [&](int tile, int buf) {
        int j0t = jbase + tile * TJ;
        cp16(adjb_u + (u32)(buf * 8192 + ((cp_row << 5) + cp_seg) * 4),
             adj + (size_t)(i0 + cp_row) * Nn + j0t + cp_seg);
        if (t < 64)
            cp16(dstb_u + (u32)(buf * 1024 + t * 16),
                 (const char*)g_dstT + ((size_t)j0t * NH + t * 4) * 4);
#pragma unroll
        for (int q = 0; q < 8; q++) {
            int idx = q * 512 + t;
            int jj = idx >> 7, c4 = (idx & 127) << 2;
            cp16(whs_u + (u32)((buf * WB + jj * CC + c4) * 4),
                 &g_Wh[(size_t)(j0t + jj) * CC + c4]);
        }
    };

    // prologue: tile 0 into buf 0
    issue_tile(0, 0);
    cp_commit();
    cp_waitall();

    u64 acc[8][4];
#pragma unroll
    for (int a = 0; a < 8; a++)
#pragma unroll
        for (int c = 0; c < 4; c++) acc[a][c] = 0ull;
    __syncthreads();

    for (int jt = 0; jt < NT3; jt++) {
        int b = jt & 1;
        int j0 = jbase + jt * TJ;
        if (jt + 1 < NT3) {
            issue_tile(jt + 1, 1 - b);
            cp_commit();
        }
        // ---- pgen: warp w owns rows r0p..r0p+3, lane = j-in-tile ----
        {
            const float* db = dst_b + b * 256;
            const int*   ab = adj_b + b * 2048;
            float4 dva = *(const float4*)&db[lane * 8];
            float4 dvb = *(const float4*)&db[lane * 8 + 4];
            float dv[8] = {dva.x, dva.y, dva.z, dva.w, dvb.x, dvb.y, dvb.z, dvb.w};
            float msk[4], sumv[4];
#pragma unroll
            for (int rr = 0; rr < 4; rr++) {
                msk[rr] = ab[(r0p + rr) * 32 + lane] > 0 ? 1.f : 0.f;
                sumv[rr] = 0.f;
            }
#pragma unroll
            for (int m = 0; m < 4; m++) {
                int h0 = 2 * m;
                float4 s0 = *(const float4*)&src_s[h0 * TI + r0p];
                float4 s1 = *(const float4*)&src_s[(h0 + 1) * TI + r0p];
                float4 z0 = *(const float4*)&zinv_s[h0 * TI + r0p];
                float4 z1 = *(const float4*)&zinv_s[(h0 + 1) * TI + r0p];
                float4 v0, v1;
                v0.x = __expf(lrelu(s0.x + dv[h0])) * z0.x * msk[0];
                v0.y = __expf(lrelu(s0.y + dv[h0])) * z0.y * msk[1];
                v0.z = __expf(lrelu(s0.z + dv[h0])) * z0.z * msk[2];
                v0.w = __expf(lrelu(s0.w + dv[h0])) * z0.w * msk[3];
                v1.x = __expf(lrelu(s1.x + dv[h0 + 1])) * z1.x * msk[0];
                v1.y = __expf(lrelu(s1.y + dv[h0 + 1])) * z1.y * msk[1];
                v1.z = __expf(lrelu(s1.z + dv[h0 + 1])) * z1.z * msk[2];
                v1.w = __expf(lrelu(s1.w + dv[h0 + 1])) * z1.w * msk[3];
                sumv[0] += v0.x + v1.x; sumv[1] += v0.y + v1.y;
                sumv[2] += v0.z + v1.z; sumv[3] += v0.w + v1.w;
                *(float4*)&p_s[lane * KSP + h0 * HS + r0p] = v0;
                *(float4*)&p_s[lane * KSP + (h0 + 1) * HS + r0p] = v1;
            }
#pragma unroll
            for (int rr = 0; rr < 4; rr++)
                avg[(size_t)(i0 + r0p + rr) * Nn + j0 + lane] = sumv[rr] * 0.125f;
        }
        __syncthreads();   // p_s ready (wh_s[b] arrived before previous barrier)
        // ---- GEMM: acc[16 rows x 4 cols] += p^T * wh ----
        const float* whb = wh_s + b * WB;
#pragma unroll 4
        for (int k = 0; k < TJ; k++) {
            const float* pb = &p_s[k * KSP + hg * HS + r0g];
            ulonglong2 a01 = *(const ulonglong2*)(pb);
            ulonglong2 a23 = *(const ulonglong2*)(pb + 4);
            ulonglong2 a45 = *(const ulonglong2*)(pb + 8);
            ulonglong2 a67 = *(const ulonglong2*)(pb + 12);
            float4 b4 = *(const float4*)&whb[k * CC + col0];
            u64 bd[4];
            asm("mov.b64 %0, {%1, %1};" : "=l"(bd[0]) : "f"(b4.x));
            asm("mov.b64 %0, {%1, %1};" : "=l"(bd[1]) : "f"(b4.y));
            asm("mov.b64 %0, {%1, %1};" : "=l"(bd[2]) : "f"(b4.z));
            asm("mov.b64 %0, {%1, %1};" : "=l"(bd[3]) : "f"(b4.w));
#pragma unroll
            for (int c = 0; c < 4; c++) {
                ffma2(acc[0][c], a01.x, bd[c]);
                ffma2(acc[1][c], a01.y, bd[c]);
                ffma2(acc[2][c], a23.x, bd[c]);
                ffma2(acc[3][c], a23.y, bd[c]);
                ffma2(acc[4][c], a45.x, bd[c]);
                ffma2(acc[5][c], a45.y, bd[c]);
                ffma2(acc[6][c], a67.x, bd[c]);
                ffma2(acc[7][c], a67.y, bd[c]);
            }
        }
        cp_waitall();
        __syncthreads();   // next-tile data visible; p_s free to overwrite
    }
    float* dst = g_hp[blockIdx.x];
#pragma unroll
    for (int rp = 0; rp < 8; rp++) {
        float2 c0 = unpk(acc[rp][0]), c1 = unpk(acc[rp][1]);
        float2 c2 = unpk(acc[rp][2]), c3 = unpk(acc[rp][3]);
        int r = i0 + r0g + rp * 2;
        *(float4*)&dst[(size_t)r * CC + col0] = make_float4(c0.x, c1.x, c2.x, c3.x);
        *(float4*)&dst[(size_t)(r + 1) * CC + col0] = make_float4(c0.y, c1.y, c2.y, c3.y);
    }
}

// ========== K4: elu + Wh2 + src2/dst2 exp tables ==========
__global__ void __launch_bounds__(128) k4_out(const float* __restrict__ Wout,
                                              const float* __restrict__ aos,
                                              const float* __restrict__ aod) {
    int w = threadIdx.x >> 5, lane = threadIdx.x & 31;
    int row = blockIdx.x * 4 + w;
    float acc[NC];
#pragma unroll
    for (int c = 0; c < NC; c++) acc[c] = 0.f;
#pragma unroll 4
    for (int m = 0; m < FIN / 32; m++) {
        int k = m * 32 + lane;
        float v = 0.f;
#pragma unroll
        for (int s = 0; s < JSPLIT; s++) v += g_hp[s][(size_t)row * CC + k];
        v = v > 0.f ? v : (__expf(v) - 1.f);
        const float4* wp = (const float4*)(Wout + (size_t)k * NC);
        float4 w0 = wp[0], w1 = wp[1], w2 = wp[2], w3 = wp[3];
        acc[0] += v * w0.x; acc[1] += v * w0.y; acc[2] += v * w0.z; acc[3] += v * w0.w;
        acc[4] += v * w1.x; acc[5] += v * w1.y; acc[6] += v * w1.z; acc[7] += v * w1.w;
        acc[8] += v * w2.x; acc[9] += v * w2.y; acc[10] += v * w2.z; acc[11] += v * w2.w;
        acc[12] += v * w3.x; acc[13] += v * w3.y; acc[14] += v * w3.z; acc[15] += v * w3.w;
    }
#pragma unroll
    for (int c = 0; c < NC; c++) {
        float v = acc[c];
#pragma unroll
        for (int o = 16; o; o >>= 1) v += __shfl_down_sync(0xffffffffu, v, o);
        acc[c] = v;
    }
    if (!lane) {
        float s = 0.f, d = 0.f;
#pragma unroll
        for (int c = 0; c < NC; c++) {
            g_Wh2[(size_t)row * NC + c] = acc[c];
            s += acc[c] * aos[c];
            d += acc[c] * aod[c];
        }
        g_s2e[row] = make_float4(s, __expf(s), __expf(LRA * s), 0.f);
        g_d2e[row] = make_float4(d, __expf(d), __expf(LRA * d), 0.f);
    }
}

// ========== K5: output attention + log_softmax ==========
__global__ void __launch_bounds__(256) k5_final(const int* __restrict__ adj,
                                                float* __restrict__ out) {
    extern __shared__ float sm5[];
    float* p = sm5;
    float* w2s = p + TI5 * Nn;
    float* red = w2s + 256 * 17;
    int i0 = blockIdx.x * TI5;
    int t = threadIdx.x, lane = t & 31, w = t >> 5;
    float zs[TI5], s2v[TI5], q1[TI5], q2[TI5];
#pragma unroll
    for (int i = 0; i < TI5; i++) {
        float4 e = g_s2e[i0 + i];
        zs[i] = 0.f; s2v[i] = e.x; q1[i] = e.y; q2[i] = e.z;
    }
    for (int j = t; j < Nn; j += 256) {
        float4 e = g_d2e[j];
#pragma unroll
        for (int i = 0; i < TI5; i++) {
            bool c = (s2v[i] + e.x) > 0.f;
            float pv = c ? q1[i] * e.y : q2[i] * e.z;
            pv = adj[(size_t)(i0 + i) * Nn + j] > 0 ? pv : 0.f;
            p[i * Nn + j] = pv;
            zs[i] += pv;
        }
    }
#pragma unroll
    for (int i = 0; i < TI5; i++) {
        float v = zs[i];
#pragma unroll
        for (int o = 16; o; o >>= 1) v += __shfl_down_sync(0xffffffffu, v, o);
        if (!lane) red[w * TI5 + i] = v;
    }
    __syncthreads();
    float Z = 0.f;
#pragma unroll
    for (int ww = 0; ww < 8; ww++) Z += red[ww * TI5 + w];
    float zinv = 1.f / Z;
    float acc[NC];
#pragma unroll
    for (int c = 0; c < NC; c++) acc[c] = 0.f;
    for (int j0 = 0; j0 < Nn; j0 += 256) {
        __syncthreads();
        {
            const float4* gw = (const float4*)&g_Wh2[(size_t)(j0 + t) * NC];
            float4 v0 = gw[0], v1 = gw[1], v2 = gw[2], v3 = gw[3];
            float* ds = &w2s[t * 17];
            ds[0] = v0.x; ds[1] = v0.y; ds[2] = v0.z; ds[3] = v0.w;
            ds[4] = v1.x; ds[5] = v1.y; ds[6] = v1.z; ds[7] = v1.w;
            ds[8] = v2.x; ds[9] = v2.y; ds[10] = v2.z; ds[11] = v2.w;
            ds[12] = v3.x; ds[13] = v3.y; ds[14] = v3.z; ds[15] = v3.w;
        }
        __syncthreads();
#pragma unroll
        for (int jj0 = 0; jj0 < 256; jj0 += 32) {
            int jj = jj0 + lane;
            float pv = p[w * Nn + j0 + jj];
            const float* wr = &w2s[jj * 17];
#pragma unroll
            for (int c = 0; c < NC; c++) acc[c] += pv * wr[c];
        }
    }
#pragma unroll
    for (int c = 0; c < NC; c++) {
        float v = acc[c];
#pragma unroll
        for (int o = 16; o; o >>= 1) v += __shfl_down_sync(0xffffffffu, v, o);
        acc[c] = v;
    }
    if (!lane) {
        float ho[NC], mx = -1e30f;
#pragma unroll
        for (int c = 0; c < NC; c++) { ho[c] = acc[c] * zinv; mx = fmaxf(mx, ho[c]); }
        float se = 0.f;
#pragma unroll
        for (int c = 0; c < NC; c++) se += __expf(ho[c] - mx);
        float lse = mx + __logf(se);
#pragma unroll
        for (int c = 0; c < NC; c++) out[(size_t)(i0 + w) * NC + c] = ho[c] - lse;
    }
}

// =======================================================================
extern "C" void kernel_launch(void* const* d_in, const int* in_sizes, int n_in,
                              void* d_out, int out_size) {
    const float* x = (const float*)d_in[0];
    const int* adj = (const int*)d_in[1];
    const float* Whd = (const float*)d_in[2];
    const float* a_src = (const float*)d_in[3];
    const float* a_dst = (const float*)d_in[4];
    const float* Wout = (const float*)d_in[5];
    const float* aos = (const float*)d_in[6];
    const float* aod = (const float*)d_in[7];
    float* out = (float*)d_out;
    float* avg = out + (size_t)Nn * NC;

    const int SMEM3 = 54912 * 4;   // 219,648 B
    const int SMEM5 = (TI5 * Nn + 256 * 17 + 64) * 4;
    cudaFuncSetAttribute(k3_att, cudaFuncAttributeMaxDynamicSharedMemorySize, SMEM3);
    cudaFuncSetAttribute(k5_final, cudaFuncAttributeMaxDynamicSharedMemorySize, SMEM5);

    k1_gemm<<<dim3(CC / 64, Nn / 64), 256>>>(x, Whd);
    k_srcdst<<<Nn, 256>>>(a_src, a_dst);
    k2_z<<<Nn, 256>>>(adj);
    k3_att<<<dim3(JSPLIT, Nn / TI), 512, SMEM3>>>(adj, avg);
    k4_out<<<Nn / 4, 128>>>(Wout, aos, aod);
    k5_final<<<Nn / TI5, 256, SMEM5>>>(adj, out);
}

// round 10
// speedup vs baseline: 1.7165x; 1.1901x over previous
#include <cuda_runtime.h>
#include <cstdint>

#define Nn   3072
#define FIN  512
#define NH   8
#define CC   512
#define NC   16
#define LRA  0.2f
#define JSPLIT 3
#define JCHUNK 1024
#define TI   64
#define TJ   32
#define NT3  32      // JCHUNK/TJ
#define KSP  516     // p_s per-j stride in floats (129 float4s -> conflict-free)
#define HS   64
#define WB   16384   // wh_s buffer stride (floats)
#define TI5  8

typedef unsigned long long u64;
typedef uint32_t u32;

// ---- static device scratch ----
__device__ float g_Wh[Nn * CC];
__device__ float g_srcT[Nn * NH], g_dstT[Nn * NH], g_Zinv[Nn * NH];
__device__ float g_hp[JSPLIT][Nn * CC];
__device__ float g_Wh2[Nn * NC];
__device__ float g_s2[Nn], g_d2[Nn];

__device__ __forceinline__ float lrelu(float x) { return fmaxf(x, LRA * x); }
__device__ __forceinline__ void ffma2(u64& d, u64 a, u64 b) {
    asm("fma.rn.f32x2 %0, %1, %2, %0;" : "+l"(d) : "l"(a), "l"(b));
}
__device__ __forceinline__ float2 unpk(u64 v) {
    float2 r;
    asm("mov.b64 {%0, %1}, %2;" : "=f"(r.x), "=f"(r.y) : "l"(v));
    return r;
}
__device__ __forceinline__ void cp16(u32 s, const void* g) {
    asm volatile("cp.async.cg.shared.global [%0], [%1], 16;" :: "r"(s), "l"(g));
}
__device__ __forceinline__ void cp_commit() {
    asm volatile("cp.async.commit_group;" ::: "memory");
}
__device__ __forceinline__ void cp_waitall() {
    asm volatile("cp.async.wait_group 0;" ::: "memory");
}

// ================= K1: Wh = x @ W (64x64 tile SGEMM, f32x2, pipelined) =====
__global__ void __launch_bounds__(256) k1_gemm(const float* __restrict__ x,
                                               const float* __restrict__ W) {
    __shared__ float As[16][64], Bs[16][64];
    int t = threadIdx.x, tx = t & 15, ty = t >> 4;
    int row0 = blockIdx.y * 64, col0 = blockIdx.x * 64;
    const float* Wb = W + (size_t)(col0 >> 6) * FIN * 64;
    int ra_r = t >> 2, ra_c = (t & 3) << 2, rb_r = t >> 4, rb_c = (t & 15) << 2;
    float4 ra = *(const float4*)&x[(size_t)(row0 + ra_r) * FIN + ra_c];
    float4 rb = *(const float4*)&Wb[(size_t)rb_r * 64 + rb_c];
    u64 acc[2][4];
#pragma unroll
    for (int i = 0; i < 2; i++)
#pragma unroll
        for (int j = 0; j < 4; j++) acc[i][j] = 0ull;
    for (int k0 = 0; k0 < FIN; k0 += 16) {
        As[ra_c][ra_r] = ra.x; As[ra_c + 1][ra_r] = ra.y;
        As[ra_c + 2][ra_r] = ra.z; As[ra_c + 3][ra_r] = ra.w;
        *(float4*)&Bs[rb_r][rb_c] = rb;
        __syncthreads();
        if (k0 + 16 < FIN) {
            ra = *(const float4*)&x[(size_t)(row0 + ra_r) * FIN + k0 + 16 + ra_c];
            rb = *(const float4*)&Wb[(size_t)(k0 + 16 + rb_r) * 64 + rb_c];
        }
#pragma unroll
        for (int k = 0; k < 16; k++) {
            ulonglong2 ap = *(const ulonglong2*)&As[k][ty * 4];
            float4 b4 = *(const float4*)&Bs[k][tx * 4];
            u64 bd[4];
            asm("mov.b64 %0, {%1, %1};" : "=l"(bd[0]) : "f"(b4.x));
            asm("mov.b64 %0, {%1, %1};" : "=l"(bd[1]) : "f"(b4.y));
            asm("mov.b64 %0, {%1, %1};" : "=l"(bd[2]) : "f"(b4.z));
            asm("mov.b64 %0, {%1, %1};" : "=l"(bd[3]) : "f"(b4.w));
#pragma unroll
            for (int c = 0; c < 4; c++) {
                ffma2(acc[0][c], ap.x, bd[c]);
                ffma2(acc[1][c], ap.y, bd[c]);
            }
        }
        __syncthreads();
    }
#pragma unroll
    for (int rp = 0; rp < 2; rp++) {
        float2 c0 = unpk(acc[rp][0]), c1 = unpk(acc[rp][1]);
        float2 c2 = unpk(acc[rp][2]), c3 = unpk(acc[rp][3]);
        int r = row0 + ty * 4 + rp * 2;
        *(float4*)&g_Wh[(size_t)r * CC + col0 + tx * 4] =
            make_float4(c0.x, c1.x, c2.x, c3.x);
        *(float4*)&g_Wh[(size_t)(r + 1) * CC + col0 + tx * 4] =
            make_float4(c0.y, c1.y, c2.y, c3.y);
    }
}

// ================= K1b: src/dst projections =================
__global__ void __launch_bounds__(256) k_srcdst(const float* __restrict__ a_src,
                                                const float* __restrict__ a_dst) {
    int n = blockIdx.x, h = threadIdx.x >> 5, lane = threadIdx.x & 31;
    const float* wh = g_Wh + (size_t)n * CC + h * 64;
    float w0 = wh[lane], w1 = wh[lane + 32];
    float s = w0 * a_src[h * 64 + lane] + w1 * a_src[h * 64 + lane + 32];
    float d = w0 * a_dst[h * 64 + lane] + w1 * a_dst[h * 64 + lane + 32];
#pragma unroll
    for (int o = 16; o; o >>= 1) {
        s += __shfl_down_sync(0xffffffffu, s, o);
        d += __shfl_down_sync(0xffffffffu, d, o);
    }
    if (!lane) { g_srcT[n * NH + h] = s; g_dstT[n * NH + h] = d; }
}

// ================= K2: softmax denominators Z[h,i] =================
__global__ void __launch_bounds__(256) k2_z(const int* __restrict__ adj) {
    int i = blockIdx.x;
    float sr[NH], sum[NH];
#pragma unroll
    for (int h = 0; h < NH; h++) { sr[h] = g_srcT[i * NH + h]; sum[h] = 0.f; }
    const int* arow = adj + (size_t)i * Nn;
    for (int j = threadIdx.x; j < Nn; j += 256) {
        if (arow[j] > 0) {
            const float4* dp = (const float4*)(g_dstT + (size_t)j * NH);
            float4 d0 = dp[0], d1 = dp[1];
            float dv[8] = {d0.x, d0.y, d0.z, d0.w, d1.x, d1.y, d1.z, d1.w};
#pragma unroll
            for (int h = 0; h < NH; h++) sum[h] += __expf(lrelu(sr[h] + dv[h]));
        }
    }
    __shared__ float red[8][NH];
    int lane = threadIdx.x & 31, w = threadIdx.x >> 5;
#pragma unroll
    for (int h = 0; h < NH; h++) {
        float v = sum[h];
#pragma unroll
        for (int o = 16; o; o >>= 1) v += __shfl_down_sync(0xffffffffu, v, o);
        if (!lane) red[w][h] = v;
    }
    __syncthreads();
    if (threadIdx.x < NH) {
        float v = 0.f;
#pragma unroll
        for (int ww = 0; ww < 8; ww++) v += red[ww][threadIdx.x];
        g_Zinv[i * NH + threadIdx.x] = 1.f / v;
    }
}

// ====== K3: fused pgen + avg write + FFMA2 (att @ Wh), full cp.async ======
// smem floats: wh_s 2x16384 [0,32768) | p_s [32768,49280) | src_s [49280,49792)
//              zinv_s [49792,50304) | dst_b 2x256 [50304,50816)
//              adj_b 2x2048 ints [50816,54912)
__global__ void __launch_bounds__(512) k3_att(const int* __restrict__ adj,
                                              float* __restrict__ avg) {
    extern __shared__ float sm[];
    float* wh_s   = sm;
    float* p_s    = sm + 32768;
    float* src_s  = sm + 49280;
    float* zinv_s = sm + 49792;
    float* dst_b  = sm + 50304;
    int*   adj_b  = (int*)(sm + 50816);

    int t = threadIdx.x;
    int i0 = blockIdx.y * TI;
    int jbase = blockIdx.x * JCHUNK;

    // transposed [h][r] fills
    src_s[(t & 7) * TI + (t >> 3)]  = g_srcT[i0 * NH + t];
    zinv_s[(t & 7) * TI + (t >> 3)] = g_Zinv[i0 * NH + t];

    int tc = t & 127, tr = t >> 7;
    int lane = t & 31, w = t >> 5;
    int r0p = w * 4;
    int r0g = tr * 16;
    int hg = tc >> 4;
    int col0 = tc * 4;

    u32 whs_u  = (u32)__cvta_generic_to_shared(wh_s);
    u32 adjb_u = (u32)__cvta_generic_to_shared(adj_b);
    u32 dstb_u = (u32)__cvta_generic_to_shared(dst_b);
    int cp_row = t >> 3, cp_seg = (t & 7) << 2;

    auto issue_tile = [&](int tile, int buf) {
        int j0t = jbase + tile * TJ;
        cp16(adjb_u + (u32)(buf * 8192 + ((cp_row << 5) + cp_seg) * 4),
             adj + (size_t)(i0 + cp_row) * Nn + j0t + cp_seg);
        if (t < 64)
            cp16(dstb_u + (u32)(buf * 1024 + t * 16),
                 (const char*)g_dstT + ((size_t)j0t * NH + t * 4) * 4);
#pragma unroll
        for (int q = 0; q < 8; q++) {
            int idx = q * 512 + t;
            int jj = idx >> 7, c4 = (idx & 127) << 2;
            cp16(whs_u + (u32)((buf * WB + jj * CC + c4) * 4),
                 &g_Wh[(size_t)(j0t + jj) * CC + c4]);
        }
    };

    // prologue: tile 0 into buf 0
    issue_tile(0, 0);
    cp_commit();
    cp_waitall();

    u64 acc[8][4];
#pragma unroll
    for (int a = 0; a < 8; a++)
#pragma unroll
        for (int c = 0; c < 4; c++) acc[a][c] = 0ull;
    __syncthreads();

    for (int jt = 0; jt < NT3; jt++) {
        int b = jt & 1;
        int j0 = jbase + jt * TJ;
        if (jt + 1 < NT3) {
            issue_tile(jt + 1, 1 - b);
            cp_commit();
        }
        // ---- pgen: warp w owns rows r0p..r0p+3, lane = j-in-tile ----
        {
            const float* db = dst_b + b * 256;
            const int*   ab = adj_b + b * 2048;
            float4 dva = *(const float4*)&db[lane * 8];
            float4 dvb = *(const float4*)&db[lane * 8 + 4];
            float dv[8] = {dva.x, dva.y, dva.z, dva.w, dvb.x, dvb.y, dvb.z, dvb.w};
            float msk[4], sumv[4];
#pragma unroll
            for (int rr = 0; rr < 4; rr++) {
                msk[rr] = ab[(r0p + rr) * 32 + lane] > 0 ? 1.f : 0.f;
                sumv[rr] = 0.f;
            }
#pragma unroll
            for (int m = 0; m < 4; m++) {
                int h0 = 2 * m;
                float4 s0 = *(const float4*)&src_s[h0 * TI + r0p];
                float4 s1 = *(const float4*)&src_s[(h0 + 1) * TI + r0p];
                float4 z0 = *(const float4*)&zinv_s[h0 * TI + r0p];
                float4 z1 = *(const float4*)&zinv_s[(h0 + 1) * TI + r0p];
                float4 v0, v1;
                v0.x = __expf(lrelu(s0.x + dv[h0])) * z0.x * msk[0];
                v0.y = __expf(lrelu(s0.y + dv[h0])) * z0.y * msk[1];
                v0.z = __expf(lrelu(s0.z + dv[h0])) * z0.z * msk[2];
                v0.w = __expf(lrelu(s0.w + dv[h0])) * z0.w * msk[3];
                v1.x = __expf(lrelu(s1.x + dv[h0 + 1])) * z1.x * msk[0];
                v1.y = __expf(lrelu(s1.y + dv[h0 + 1])) * z1.y * msk[1];
                v1.z = __expf(lrelu(s1.z + dv[h0 + 1])) * z1.z * msk[2];
                v1.w = __expf(lrelu(s1.w + dv[h0 + 1])) * z1.w * msk[3];
                sumv[0] += v0.x + v1.x; sumv[1] += v0.y + v1.y;
                sumv[2] += v0.z + v1.z; sumv[3] += v0.w + v1.w;
                *(float4*)&p_s[lane * KSP + h0 * HS + r0p] = v0;
                *(float4*)&p_s[lane * KSP + (h0 + 1) * HS + r0p] = v1;
            }
#pragma unroll
            for (int rr = 0; rr < 4; rr++)
                avg[(size_t)(i0 + r0p + rr) * Nn + j0 + lane] = sumv[rr] * 0.125f;
        }
        __syncthreads();   // p_s ready (wh_s[b] arrived before previous barrier)
        // ---- GEMM: acc[16 rows x 4 cols] += p^T * wh ----
        const float* whb = wh_s + b * WB;
#pragma unroll 4
        for (int k = 0; k < TJ; k++) {
            const float* pb = &p_s[k * KSP + hg * HS + r0g];
            ulonglong2 a01 = *(const ulonglong2*)(pb);
            ulonglong2 a23 = *(const ulonglong2*)(pb + 4);
            ulonglong2 a45 = *(const ulonglong2*)(pb + 8);
            ulonglong2 a67 = *(const ulonglong2*)(pb + 12);
            float4 b4 = *(const float4*)&whb[k * CC + col0];
            u64 bd[4];
            asm("mov.b64 %0, {%1, %1};" : "=l"(bd[0]) : "f"(b4.x));
            asm("mov.b64 %0, {%1, %1};" : "=l"(bd[1]) : "f"(b4.y));
            asm("mov.b64 %0, {%1, %1};" : "=l"(bd[2]) : "f"(b4.z));
            asm("mov.b64 %0, {%1, %1};" : "=l"(bd[3]) : "f"(b4.w));
#pragma unroll
            for (int c = 0; c < 4; c++) {
                ffma2(acc[0][c], a01.x, bd[c]);
                ffma2(acc[1][c], a01.y, bd[c]);
                ffma2(acc[2][c], a23.x, bd[c]);
                ffma2(acc[3][c], a23.y, bd[c]);
                ffma2(acc[4][c], a45.x, bd[c]);
                ffma2(acc[5][c], a45.y, bd[c]);
                ffma2(acc[6][c], a67.x, bd[c]);
                ffma2(acc[7][c], a67.y, bd[c]);
            }
        }
        cp_waitall();
        __syncthreads();   // next-tile data visible; p_s free to overwrite
    }
    float* dst = g_hp[blockIdx.x];
#pragma unroll
    for (int rp = 0; rp < 8; rp++) {
        float2 c0 = unpk(acc[rp][0]), c1 = unpk(acc[rp][1]);
        float2 c2 = unpk(acc[rp][2]), c3 = unpk(acc[rp][3]);
        int r = i0 + r0g + rp * 2;
        *(float4*)&dst[(size_t)r * CC + col0] = make_float4(c0.x, c1.x, c2.x, c3.x);
        *(float4*)&dst[(size_t)(r + 1) * CC + col0] = make_float4(c0.y, c1.y, c2.y, c3.y);
    }
}

// ====== K4: elu + Wh2 = x2 @ W_out + src2/dst2 (round-2 form) ======
__global__ void __launch_bounds__(128) k4_out(const float* __restrict__ Wout,
                                              const float* __restrict__ aos,
                                              const float* __restrict__ aod) {
    int w = threadIdx.x >> 5, lane = threadIdx.x & 31;
    int row = blockIdx.x * 4 + w;
    const float* h0 = g_hp[0] + (size_t)row * CC;
    const float* h1 = g_hp[1] + (size_t)row * CC;
    const float* h2 = g_hp[2] + (size_t)row * CC;
    float acc[NC];
#pragma unroll
    for (int c = 0; c < NC; c++) acc[c] = 0.f;
#pragma unroll 4
    for (int m = 0; m < FIN / 32; m++) {
        int k = m * 32 + lane;
        float v = h0[k] + h1[k] + h2[k];
        v = v > 0.f ? v : (__expf(v) - 1.f);   // elu
        const float4* wp = (const float4*)(Wout + (size_t)k * NC);
        float4 w0 = wp[0], w1 = wp[1], w2 = wp[2], w3 = wp[3];
        acc[0] += v * w0.x; acc[1] += v * w0.y; acc[2] += v * w0.z; acc[3] += v * w0.w;
        acc[4] += v * w1.x; acc[5] += v * w1.y; acc[6] += v * w1.z; acc[7] += v * w1.w;
        acc[8] += v * w2.x; acc[9] += v * w2.y; acc[10] += v * w2.z; acc[11] += v * w2.w;
        acc[12] += v * w3.x; acc[13] += v * w3.y; acc[14] += v * w3.z; acc[15] += v * w3.w;
    }
#pragma unroll
    for (int c = 0; c < NC; c++) {
        float v = acc[c];
#pragma unroll
        for (int o = 16; o; o >>= 1) v += __shfl_down_sync(0xffffffffu, v, o);
        acc[c] = v;
    }
    if (!lane) {
        float s = 0.f, d = 0.f;
#pragma unroll
        for (int c = 0; c < NC; c++) {
            g_Wh2[(size_t)row * NC + c] = acc[c];
            s += acc[c] * aos[c];
            d += acc[c] * aod[c];
        }
        g_s2[row] = s;
        g_d2[row] = d;
    }
}

// ====== K5: output attention + log_softmax (round-2 form) ======
__global__ void __launch_bounds__(256) k5_final(const int* __restrict__ adj,
                                                float* __restrict__ out) {
    extern __shared__ float sm5[];
    float* p   = sm5;                 // TI5*Nn
    float* w2s = p + TI5 * Nn;        // 256*17
    float* red = w2s + 256 * 17;      // 64
    int i0 = blockIdx.x * TI5;
    int t = threadIdx.x, lane = t & 31, w = t >> 5;

    float zs[TI5], s2v[TI5];
#pragma unroll
    for (int i = 0; i < TI5; i++) { zs[i] = 0.f; s2v[i] = g_s2[i0 + i]; }
    for (int j = t; j < Nn; j += 256) {
        float dv = g_d2[j];
#pragma unroll
        for (int i = 0; i < TI5; i++) {
            float pv = 0.f;
            if (adj[(size_t)(i0 + i) * Nn + j] > 0)
                pv = __expf(lrelu(s2v[i] + dv));
            p[i * Nn + j] = pv;
            zs[i] += pv;
        }
    }
#pragma unroll
    for (int i = 0; i < TI5; i++) {
        float v = zs[i];
#pragma unroll
        for (int o = 16; o; o >>= 1) v += __shfl_down_sync(0xffffffffu, v, o);
        if (!lane) red[w * TI5 + i] = v;
    }
    __syncthreads();
    float Z = 0.f;
#pragma unroll
    for (int ww = 0; ww < 8; ww++) Z += red[ww * TI5 + w];
    float zinv = 1.f / Z;

    float acc[NC];
#pragma unroll
    for (int c = 0; c < NC; c++) acc[c] = 0.f;
    for (int j0 = 0; j0 < Nn; j0 += 256) {
        __syncthreads();
        {
            const float4* gw = (const float4*)&g_Wh2[(size_t)(j0 + t) * NC];
            float4 v0 = gw[0], v1 = gw[1], v2 = gw[2], v3 = gw[3];
            float* ds = &w2s[t * 17];
            ds[0] = v0.x; ds[1] = v0.y; ds[2] = v0.z; ds[3] = v0.w;
            ds[4] = v1.x; ds[5] = v1.y; ds[6] = v1.z; ds[7] = v1.w;
            ds[8] = v2.x; ds[9] = v2.y; ds[10] = v2.z; ds[11] = v2.w;
            ds[12] = v3.x; ds[13] = v3.y; ds[14] = v3.z; ds[15] = v3.w;
        }
        __syncthreads();
#pragma unroll
        for (int jj0 = 0; jj0 < 256; jj0 += 32) {
            int jj = jj0 + lane;
            float pv = p[w * Nn + j0 + jj];
            const float* wr = &w2s[jj * 17];
#pragma unroll
            for (int c = 0; c < NC; c++) acc[c] += pv * wr[c];
        }
    }
#pragma unroll
    for (int c = 0; c < NC; c++) {
        float v = acc[c];
#pragma unroll
        for (int o = 16; o; o >>= 1) v += __shfl_down_sync(0xffffffffu, v, o);
        acc[c] = v;
    }
    if (!lane) {
        float ho[NC];
        float mx = -1e30f;
#pragma unroll
        for (int c = 0; c < NC; c++) { ho[c] = acc[c] * zinv; mx = fmaxf(mx, ho[c]); }
        float se = 0.f;
#pragma unroll
        for (int c = 0; c < NC; c++) se += __expf(ho[c] - mx);
        float lse = mx + __logf(se);
#pragma unroll
        for (int c = 0; c < NC; c++) out[(size_t)(i0 + w) * NC + c] = ho[c] - lse;
    }
}

// =======================================================================
extern "C" void kernel_launch(void* const* d_in, const int* in_sizes, int n_in,
                              void* d_out, int out_size) {
    const float* x = (const float*)d_in[0];
    const int* adj = (const int*)d_in[1];
    const float* Whd = (const float*)d_in[2];
    const float* a_src = (const float*)d_in[3];
    const float* a_dst = (const float*)d_in[4];
    const float* Wout = (const float*)d_in[5];
    const float* aos = (const float*)d_in[6];
    const float* aod = (const float*)d_in[7];
    float* out = (float*)d_out;
    float* avg = out + (size_t)Nn * NC;

    const int SMEM3 = 54912 * 4;   // 219,648 B
    const int SMEM5 = (TI5 * Nn + 256 * 17 + 64) * 4;
    cudaFuncSetAttribute(k3_att, cudaFuncAttributeMaxDynamicSharedMemorySize, SMEM3);
    cudaFuncSetAttribute(k5_final, cudaFuncAttributeMaxDynamicSharedMemorySize, SMEM5);

    k1_gemm<<<dim3(CC / 64, Nn / 64), 256>>>(x, Whd);
    k_srcdst<<<Nn, 256>>>(a_src, a_dst);
    k2_z<<<Nn, 256>>>(adj);
    k3_att<<<dim3(JSPLIT, Nn / TI), 512, SMEM3>>>(adj, avg);
    k4_out<<<Nn / 4, 128>>>(Wout, aos, aod);
    k5_final<<<Nn / TI5, 256, SMEM5>>>(adj, out);
}